// round 1
// baseline (speedup 1.0000x reference)
#include <cuda_runtime.h>
#include <math.h>

#define T_SEQ 2048
#define BATCH 2
#define EMB   1024
#define NH    16
#define DH    64
#define NTOK  (BATCH * T_SEQ)   // 4096

// Scratch (allocation-free rule: __device__ globals)
__device__ float g_Q[(size_t)NTOK * EMB];  // [B,H,T,Dh]
__device__ float g_K[(size_t)NTOK * EMB];
__device__ float g_V[(size_t)NTOK * EMB];
__device__ float g_O[(size_t)NTOK * EMB];  // [B,T,E] merged attention output

// ---------------------------------------------------------------------------
// Projection GEMM:  Y[m,n] = sum_k X[m,k] * W[n,k]   (NT, both K-major)
// MODE 0/1/2: X = param, Y = g_Q/g_K/g_V in [B,H,T,Dh] layout
// MODE 3:     X = g_O,   Y = param (d_out), flat [NTOK, EMB]
// 128x128x16 tile, 256 threads, 8x8 register tile per thread.
// ---------------------------------------------------------------------------
template <int MODE>
__global__ void __launch_bounds__(256, 2)
proj_kernel(const float* __restrict__ Xp, const float* __restrict__ W,
            float* __restrict__ Yp)
{
    constexpr int BM = 128, BN = 128, BK = 16;
    __shared__ float As[BK][BM + 4];
    __shared__ float Bs[BK][BN + 4];

    const float* X = (MODE == 3) ? (const float*)g_O : Xp;
    float* Y = (MODE == 0) ? g_Q : (MODE == 1) ? g_K : (MODE == 2) ? g_V : Yp;

    const int m0 = blockIdx.y * BM;
    const int n0 = blockIdx.x * BN;
    const int t  = threadIdx.x;      // 0..255
    const int tx = t & 15;
    const int ty = t >> 4;

    float acc[8][8];
#pragma unroll
    for (int i = 0; i < 8; i++)
#pragma unroll
        for (int j = 0; j < 8; j++) acc[i][j] = 0.f;

    for (int k0 = 0; k0 < EMB; k0 += BK) {
        // Load A and B tiles (transposed to k-major in smem)
#pragma unroll
        for (int s = 0; s < 2; s++) {
            int i   = t + s * 256;        // 0..511
            int row = i >> 2;             // 0..127
            int k4  = (i & 3) << 2;       // 0,4,8,12
            float4 fa = *(const float4*)(X + (size_t)(m0 + row) * EMB + k0 + k4);
            As[k4 + 0][row] = fa.x; As[k4 + 1][row] = fa.y;
            As[k4 + 2][row] = fa.z; As[k4 + 3][row] = fa.w;
            float4 fb = *(const float4*)(W + (size_t)(n0 + row) * EMB + k0 + k4);
            Bs[k4 + 0][row] = fb.x; Bs[k4 + 1][row] = fb.y;
            Bs[k4 + 2][row] = fb.z; Bs[k4 + 3][row] = fb.w;
        }
        __syncthreads();

#pragma unroll
        for (int kk = 0; kk < BK; kk++) {
            float a[8], b[8];
            *(float4*)&a[0] = *(const float4*)&As[kk][ty * 8];
            *(float4*)&a[4] = *(const float4*)&As[kk][ty * 8 + 4];
            *(float4*)&b[0] = *(const float4*)&Bs[kk][tx * 8];
            *(float4*)&b[4] = *(const float4*)&Bs[kk][tx * 8 + 4];
#pragma unroll
            for (int i = 0; i < 8; i++)
#pragma unroll
                for (int j = 0; j < 8; j++)
                    acc[i][j] = fmaf(a[i], b[j], acc[i][j]);
        }
        __syncthreads();
    }

    // Epilogue
#pragma unroll
    for (int i = 0; i < 8; i++) {
        const int m = m0 + ty * 8 + i;
#pragma unroll
        for (int j = 0; j < 8; j++) {
            const int n = n0 + tx * 8 + j;
            if (MODE == 3) {
                Y[(size_t)m * EMB + n] = acc[i][j];
            } else {
                const int b = m / T_SEQ, tt = m % T_SEQ;
                const int h = n >> 6, d = n & 63;
                Y[((size_t)(b * NH + h) * T_SEQ + tt) * DH + d] = acc[i][j];
            }
        }
    }
}

// ---------------------------------------------------------------------------
// Flash attention (causal), fp32.
// One block: 64 queries of one (b,h). 256 threads as 16x16; 4x4 micro-tiles.
// Loops key tiles kt = 0..qt (causal skip above diagonal).
// Dynamic smem: Qs[64][68] + Ks[64][68] + Vs[64][68] + Ps[64][68] = 69632 B.
// ---------------------------------------------------------------------------
__global__ void __launch_bounds__(256)
attn_kernel()
{
    constexpr int BM = 64, BN = 64, LD = BM + 4;  // LD=68, float4-aligned rows
    extern __shared__ float smem[];
    float (*Qs)[LD] = (float (*)[LD])(smem);                 // [DH][LD] d-major
    float (*Ks)[LD] = (float (*)[LD])(smem + DH * LD);       // [DH][LD] d-major
    float (*Vs)[LD] = (float (*)[LD])(smem + 2 * DH * LD);   // [BN][LD] k-major (cols=d)
    float (*Ps)[LD] = (float (*)[LD])(smem + 3 * DH * LD);   // [BN][LD] key-major (cols=q)

    const int bh = blockIdx.y;
    const int qt = gridDim.x - 1 - blockIdx.x;   // heavy tiles scheduled first
    const int q0 = qt * BM;
    const int t  = threadIdx.x;
    const int tx = t & 15;
    const int ty = t >> 4;

    const float* Qg = g_Q + (size_t)bh * T_SEQ * DH;
    const float* Kg = g_K + (size_t)bh * T_SEQ * DH;
    const float* Vg = g_V + (size_t)bh * T_SEQ * DH;

    // Load resident Q tile (transposed to d-major)
#pragma unroll
    for (int s = 0; s < 4; s++) {
        int i   = t + s * 256;        // 0..1023
        int row = i >> 4;             // 0..63
        int d4  = (i & 15) << 2;      // 0..60
        float4 f = *(const float4*)(Qg + (size_t)(q0 + row) * DH + d4);
        Qs[d4 + 0][row] = f.x; Qs[d4 + 1][row] = f.y;
        Qs[d4 + 2][row] = f.z; Qs[d4 + 3][row] = f.w;
    }

    float m_i[4], l_i[4], acc[4][4];
#pragma unroll
    for (int i = 0; i < 4; i++) {
        m_i[i] = -1e30f;
        l_i[i] = 0.f;
#pragma unroll
        for (int j = 0; j < 4; j++) acc[i][j] = 0.f;
    }
    const float scale = 0.125f;  // 1/sqrt(64)

    __syncthreads();

    for (int kt = 0; kt <= qt; kt++) {
        const int k0 = kt * BN;
        // Load K tile (d-major) and V tile (k-major)
#pragma unroll
        for (int s = 0; s < 4; s++) {
            int i   = t + s * 256;
            int row = i >> 4;
            int d4  = (i & 15) << 2;
            float4 f = *(const float4*)(Kg + (size_t)(k0 + row) * DH + d4);
            Ks[d4 + 0][row] = f.x; Ks[d4 + 1][row] = f.y;
            Ks[d4 + 2][row] = f.z; Ks[d4 + 3][row] = f.w;
            float4 g = *(const float4*)(Vg + (size_t)(k0 + row) * DH + d4);
            *(float4*)&Vs[row][d4] = g;
        }
        __syncthreads();

        // S = Q * K^T  (per-thread 4x4)
        float S[4][4];
#pragma unroll
        for (int i = 0; i < 4; i++)
#pragma unroll
            for (int j = 0; j < 4; j++) S[i][j] = 0.f;

#pragma unroll 8
        for (int d = 0; d < DH; d++) {
            float4 qa = *(const float4*)&Qs[d][ty * 4];
            float4 kb = *(const float4*)&Ks[d][tx * 4];
            const float a[4] = {qa.x, qa.y, qa.z, qa.w};
            const float b[4] = {kb.x, kb.y, kb.z, kb.w};
#pragma unroll
            for (int i = 0; i < 4; i++)
#pragma unroll
                for (int j = 0; j < 4; j++)
                    S[i][j] = fmaf(a[i], b[j], S[i][j]);
        }

        // Scale + causal mask (diagonal tile only)
#pragma unroll
        for (int i = 0; i < 4; i++) {
            const int qg = q0 + ty * 4 + i;
#pragma unroll
            for (int j = 0; j < 4; j++) {
                const int kg = k0 + tx * 4 + j;
                S[i][j] = (kt == qt && kg > qg) ? -1e30f : S[i][j] * scale;
            }
        }

        // Online softmax (row reductions across tx via 16-lane shuffles)
#pragma unroll
        for (int i = 0; i < 4; i++) {
            float rm = S[i][0];
            rm = fmaxf(rm, S[i][1]); rm = fmaxf(rm, S[i][2]); rm = fmaxf(rm, S[i][3]);
#pragma unroll
            for (int m = 1; m < 16; m <<= 1)
                rm = fmaxf(rm, __shfl_xor_sync(0xffffffffu, rm, m));
            const float mn    = fmaxf(m_i[i], rm);
            const float alpha = __expf(m_i[i] - mn);
            float rs = 0.f;
#pragma unroll
            for (int j = 0; j < 4; j++) {
                S[i][j] = __expf(S[i][j] - mn);
                rs += S[i][j];
            }
#pragma unroll
            for (int m = 1; m < 16; m <<= 1)
                rs += __shfl_xor_sync(0xffffffffu, rs, m);
            l_i[i] = l_i[i] * alpha + rs;
            m_i[i] = mn;
#pragma unroll
            for (int j = 0; j < 4; j++) acc[i][j] *= alpha;
        }

        // Stage P (transposed to key-major) for the PV GEMM
#pragma unroll
        for (int i = 0; i < 4; i++)
#pragma unroll
            for (int j = 0; j < 4; j++)
                Ps[tx * 4 + j][ty * 4 + i] = S[i][j];
        __syncthreads();

        // acc += P * V
#pragma unroll 8
        for (int k = 0; k < BN; k++) {
            float4 pv = *(const float4*)&Ps[k][ty * 4];
            float4 vv = *(const float4*)&Vs[k][tx * 4];
            const float p[4] = {pv.x, pv.y, pv.z, pv.w};
            const float v4[4] = {vv.x, vv.y, vv.z, vv.w};
#pragma unroll
            for (int i = 0; i < 4; i++)
#pragma unroll
                for (int j = 0; j < 4; j++)
                    acc[i][j] = fmaf(p[i], v4[j], acc[i][j]);
        }
        __syncthreads();  // protect Ks/Vs/Ps before next tile's loads
    }

    // Epilogue: normalize, write merged [B,T,E] layout
    const int b = bh / NH, h = bh % NH;
#pragma unroll
    for (int i = 0; i < 4; i++) {
        const float inv = 1.0f / l_i[i];
        const int q = q0 + ty * 4 + i;
        float4 o;
        o.x = acc[i][0] * inv; o.y = acc[i][1] * inv;
        o.z = acc[i][2] * inv; o.w = acc[i][3] * inv;
        *(float4*)&g_O[(size_t)(b * T_SEQ + q) * EMB + h * DH + tx * 4] = o;
    }
}

// ---------------------------------------------------------------------------
extern "C" void kernel_launch(void* const* d_in, const int* in_sizes, int n_in,
                              void* d_out, int out_size)
{
    (void)in_sizes; (void)n_in; (void)out_size;
    const float* q  = (const float*)d_in[0];
    const float* k  = (const float*)d_in[1];
    const float* v  = (const float*)d_in[2];
    const float* Wq = (const float*)d_in[3];
    const float* Wk = (const float*)d_in[4];
    const float* Wv = (const float*)d_in[5];
    const float* Wo = (const float*)d_in[6];
    float* out = (float*)d_out;

    static bool attr_set = false;
    if (!attr_set) {
        cudaFuncSetAttribute(attn_kernel,
                             cudaFuncAttributeMaxDynamicSharedMemorySize,
                             4 * DH * (64 + 4) * (int)sizeof(float));
        attr_set = true;
    }

    const dim3 gproj(EMB / 128, NTOK / 128);       // (8, 32)
    proj_kernel<0><<<gproj, 256>>>(q, Wq, nullptr);
    proj_kernel<1><<<gproj, 256>>>(k, Wk, nullptr);
    proj_kernel<2><<<gproj, 256>>>(v, Wv, nullptr);

    const dim3 gattn(T_SEQ / 64, BATCH * NH);      // (32, 32)
    attn_kernel<<<gattn, 256, 4 * DH * (64 + 4) * (int)sizeof(float)>>>();

    proj_kernel<3><<<gproj, 256>>>(nullptr, Wo, out);
}